// round 2
// baseline (speedup 1.0000x reference)
#include <cuda_runtime.h>
#include <cstdint>

// out[v] = sum over edges (u->v) of emb[u], D_FEAT = 64 fp32 per row.
// NOTE: reference uses jnp.int64 but without jax_enable_x64 JAX silently
// produces int32 — indices are int32 on device.
//
// 16 threads cooperate per edge; each thread owns one float4 (16B) chunk of
// the 256B feature row: fully coalesced gather, vector no-return reduction
// scatter (red.global.add.v4.f32, 4x fewer L2 atomic ops than scalar).

static constexpr int D_FEAT = 64;
static constexpr int VEC_PER_ROW = D_FEAT / 4;  // 16 float4 per row

__global__ void edge_scatter_sum_kernel(const float4* __restrict__ emb,
                                        const int* __restrict__ src,
                                        const int* __restrict__ dst,
                                        float* __restrict__ out,
                                        int n_edges) {
    long long t = (long long)blockIdx.x * blockDim.x + threadIdx.x;
    int e = (int)(t >> 4);        // edge index
    int c = (int)(t & 15);        // float4 chunk within the row
    if (e >= n_edges) return;

    int s = src[e];
    int d = dst[e];

    float4 v = emb[(long long)s * VEC_PER_ROW + c];
    float* p = out + ((long long)d * D_FEAT + c * 4);

    asm volatile("red.global.add.v4.f32 [%0], {%1, %2, %3, %4};"
                 :: "l"(p), "f"(v.x), "f"(v.y), "f"(v.z), "f"(v.w)
                 : "memory");
}

extern "C" void kernel_launch(void* const* d_in, const int* in_sizes, int n_in,
                              void* d_out, int out_size) {
    const float4* emb = (const float4*)d_in[0];
    const int*    src = (const int*)d_in[1];
    const int*    dst = (const int*)d_in[2];
    float* out = (float*)d_out;

    int n_edges = in_sizes[1];  // src element count

    // Output is poisoned by the harness; zero it (async memset is graph-capturable).
    cudaMemsetAsync(d_out, 0, (size_t)out_size * sizeof(float));

    long long total_threads = (long long)n_edges * 16;
    int block = 256;
    int grid = (int)((total_threads + block - 1) / block);
    edge_scatter_sum_kernel<<<grid, block>>>(emb, src, dst, out, n_edges);
}